// round 12
// baseline (speedup 1.0000x reference)
#include <cuda_runtime.h>
#include <math.h>

#define NS 2048

// ---- scratch (device globals) ----
__device__ float g_R[NS * 12];           // rotation (stride 12 for float4 reads)
__device__ float g_Lq[NS * 12];          // Lambda_q
__device__ float g_Lp[NS * 12];          // Lambda_p
__device__ float g_sm[8 * NS * 12];      // softmax partials [e][site][10 of 12]
__device__ float g_colp[NS * 128];       // colsum partials [j][rg]
__device__ float g_Cpart[8 * NS * 12];   // beta@S partials [chunk][row][9 of 12]

// ---- packed f32x2 helpers ----
typedef unsigned long long ull;
__device__ __forceinline__ ull pk2(float a, float b) {
    ull r; asm("mov.b64 %0, {%1,%2};" : "=l"(r) : "f"(a), "f"(b)); return r;
}
__device__ __forceinline__ void upk2(ull p, float& a, float& b) {
    asm("mov.b64 {%0,%1}, %2;" : "=f"(a), "=f"(b) : "l"(p));
}
__device__ __forceinline__ ull fma2(ull a, ull b, ull c) {
    ull r; asm("fma.rn.f32x2 %0, %1, %2, %3;" : "=l"(r) : "l"(a), "l"(b), "l"(c)); return r;
}
__device__ __forceinline__ ull mul2(ull a, ull b) {
    ull r; asm("mul.rn.f32x2 %0, %1, %2;" : "=l"(r) : "l"(a), "l"(b)); return r;
}
__device__ __forceinline__ ull add2(ull a, ull b) {
    ull r; asm("add.rn.f32x2 %0, %1, %2;" : "=l"(r) : "l"(a), "l"(b)); return r;
}
__device__ __forceinline__ float ex2f(float x) {
    float r; asm("ex2.approx.f32 %0, %1;" : "=f"(r) : "f"(x)); return r;
}

// ---- 3x3 helpers ----
__device__ __forceinline__ void inv3(const float* a, float* o) {
    float c00 = a[4] * a[8] - a[5] * a[7];
    float c01 = a[5] * a[6] - a[3] * a[8];
    float c02 = a[3] * a[7] - a[4] * a[6];
    float det = a[0] * c00 + a[1] * c01 + a[2] * c02;
    float id = 1.0f / det;
    o[0] = c00 * id;
    o[1] = (a[2] * a[7] - a[1] * a[8]) * id;
    o[2] = (a[1] * a[5] - a[2] * a[4]) * id;
    o[3] = c01 * id;
    o[4] = (a[0] * a[8] - a[2] * a[6]) * id;
    o[5] = (a[2] * a[3] - a[0] * a[5]) * id;
    o[6] = c02 * id;
    o[7] = (a[1] * a[6] - a[0] * a[7]) * id;
    o[8] = (a[0] * a[4] - a[1] * a[3]) * id;
}
__device__ __forceinline__ void mm3(const float* A, const float* B, float* O) {
#pragma unroll
    for (int r = 0; r < 3; r++)
#pragma unroll
        for (int c = 0; c < 3; c++)
            O[r * 3 + c] = A[r * 3 + 0] * B[0 + c] + A[r * 3 + 1] * B[3 + c] + A[r * 3 + 2] * B[6 + c];
}
__device__ __forceinline__ void mTm3(const float* A, const float* B, float* O) {
#pragma unroll
    for (int r = 0; r < 3; r++)
#pragma unroll
        for (int c = 0; c < 3; c++)
            O[r * 3 + c] = A[0 + r] * B[0 + c] + A[3 + r] * B[3 + c] + A[6 + r] * B[6 + c];
}
__device__ __forceinline__ void mmT3(const float* A, const float* B, float* O) {
#pragma unroll
    for (int r = 0; r < 3; r++)
#pragma unroll
        for (int c = 0; c < 3; c++)
            O[r * 3 + c] = A[r * 3 + 0] * B[c * 3 + 0] + A[r * 3 + 1] * B[c * 3 + 1] + A[r * 3 + 2] * B[c * 3 + 2];
}
__device__ __forceinline__ void rodrigues(float x, float y, float z, float* R) {
    float t2 = x * x + y * y + z * z;
    float A, B;
    if (t2 < 1e-12f) {
        A = 1.0f - t2 * (1.0f / 6.0f);
        B = 0.5f - t2 * (1.0f / 24.0f);
    } else {
        float t = sqrtf(t2);
        A = sinf(t) / t;
        B = (1.0f - cosf(t)) / t2;
    }
    R[0] = 1.0f - B * (y * y + z * z);
    R[1] = -A * z + B * x * y;
    R[2] = A * y + B * x * z;
    R[3] = A * z + B * x * y;
    R[4] = 1.0f - B * (x * x + z * z);
    R[5] = -A * x + B * y * z;
    R[6] = -A * y + B * x * z;
    R[7] = A * x + B * y * z;
    R[8] = 1.0f - B * (x * x + y * y);
}

// compute S = R^T inv(Sq+eps) R for one site
__device__ __forceinline__ void site_S(const float* __restrict__ Sq,
                                       const float* __restrict__ phi,
                                       int site, float* Smat) {
    float a[9], Lq[9];
#pragma unroll
    for (int k = 0; k < 9; k++) a[k] = Sq[site * 9 + k];
    a[0] += 1e-6f; a[4] += 1e-6f; a[8] += 1e-6f;
    inv3(a, Lq);
    float R[9];
    rodrigues(phi[site * 3 + 0], phi[site * 3 + 1], phi[site * 3 + 2], R);
    float T[9];
    mm3(Lq, R, T);
    mTm3(R, T, Smat);
}

// ==== MEGA kernel ====
// blocks 0..1023   : beta@S GEMM partials + colsum partials (local S)
// blocks 1024..1031: geometry for the final kernel (Lp, Lq, R)
// blocks 1032..1543: softmax partial stats (4 sites/warp, 9 product planes, V/8)
__global__ void __launch_bounds__(256) mega_kernel(
    const float* __restrict__ Sp, const float* __restrict__ Sq,
    const float* __restrict__ phi, const float* __restrict__ mu,
    const float* __restrict__ W, const float* __restrict__ beta) {
    __shared__ float buf[9216];

    if (blockIdx.x < 1024) {
        // ---------------- GEMM + colsum partials ----------------
        const int t = blockIdx.x;
        const int chunk = t & 7;
        const int rg = t >> 3;
        const int j0 = chunk * 256;
        const int warp = threadIdx.x >> 5;
        const int lane = threadIdx.x & 31;
        const int row0 = rg * 16 + warp * 2;

        float* sS = buf;            // [9][264]
        float* scol = buf + 2400;   // [8][264]

        {
            float Smat[9];
            site_S(Sq, phi, j0 + threadIdx.x, Smat);
#pragma unroll
            for (int k = 0; k < 9; k++) sS[k * 264 + threadIdx.x] = Smat[k];
        }
        __syncthreads();

        const int jj = lane * 8;
        const float* b0p = beta + (size_t)row0 * NS + j0 + jj;
        const float* b1p = b0p + NS;
        ulonglong2 b0 = *(const ulonglong2*)b0p;
        ulonglong2 b0h = *(const ulonglong2*)(b0p + 4);
        ulonglong2 b1 = *(const ulonglong2*)b1p;
        ulonglong2 b1h = *(const ulonglong2*)(b1p + 4);

        float c[2][9];
#pragma unroll
        for (int k = 0; k < 9; k++) {
            ulonglong2 sa = *(const ulonglong2*)&sS[k * 264 + jj];
            ulonglong2 sb = *(const ulonglong2*)&sS[k * 264 + jj + 4];
            ull a0 = fma2(b0.x, sa.x, mul2(b0.y, sa.y));
            a0 = fma2(b0h.x, sb.x, a0);
            a0 = fma2(b0h.y, sb.y, a0);
            ull a1 = fma2(b1.x, sa.x, mul2(b1.y, sa.y));
            a1 = fma2(b1h.x, sb.x, a1);
            a1 = fma2(b1h.y, sb.y, a1);
            float lo, hi;
            upk2(a0, lo, hi);
            c[0][k] = lo + hi;
            upk2(a1, lo, hi);
            c[1][k] = lo + hi;
        }

        {
            ull c0 = add2(b0.x, b1.x);
            ull c1 = add2(b0.y, b1.y);
            ull c2 = add2(b0h.x, b1h.x);
            ull c3 = add2(b0h.y, b1h.y);
            float* dst = scol + warp * 264 + jj;
            float lo, hi;
            upk2(c0, lo, hi); dst[0] = lo; dst[1] = hi;
            upk2(c1, lo, hi); dst[2] = lo; dst[3] = hi;
            upk2(c2, lo, hi); dst[4] = lo; dst[5] = hi;
            upk2(c3, lo, hi); dst[6] = lo; dst[7] = hi;
        }

#pragma unroll
        for (int r = 0; r < 2; r++)
#pragma unroll
            for (int k = 0; k < 9; k++)
#pragma unroll
                for (int off = 16; off; off >>= 1)
                    c[r][k] += __shfl_xor_sync(~0u, c[r][k], off);

        if (lane < 2) {
            const int row = row0 + lane;
            float* dst = g_Cpart + ((size_t)chunk * NS + row) * 12;
#pragma unroll
            for (int k = 0; k < 9; k++) dst[k] = c[lane][k];
        }

        __syncthreads();
        {
            float s = 0.f;
#pragma unroll
            for (int w = 0; w < 8; w++) s += scol[w * 264 + threadIdx.x];
            g_colp[(size_t)(j0 + threadIdx.x) * 128 + rg] = s;
        }
        return;
    }

    if (blockIdx.x < 1032) {
        // ---------------- geometry ----------------
        const int site = (blockIdx.x - 1024) * 256 + threadIdx.x;
        float a[9], Lp[9], Lq[9];
#pragma unroll
        for (int k = 0; k < 9; k++) a[k] = Sp[site * 9 + k];
        a[0] += 1e-6f; a[4] += 1e-6f; a[8] += 1e-6f;
        inv3(a, Lp);
#pragma unroll
        for (int k = 0; k < 9; k++) a[k] = Sq[site * 9 + k];
        a[0] += 1e-6f; a[4] += 1e-6f; a[8] += 1e-6f;
        inv3(a, Lq);
        float R[9];
        rodrigues(phi[site * 3 + 0], phi[site * 3 + 1], phi[site * 3 + 2], R);
#pragma unroll
        for (int k = 0; k < 9; k++) {
            g_R[site * 12 + k] = R[k];
            g_Lq[site * 12 + k] = Lq[k];
            g_Lp[site * 12 + k] = Lp[k];
        }
        return;
    }

    // ---------------- softmax (V/8 split, 4 sites/warp, 9 planes) ----------------
    {
        const int b2 = blockIdx.x - 1032;
        const int e = b2 & 7;          // V-eighth
        const int sg = b2 >> 3;        // 0..63 (32 sites per group)
        const int warp = threadIdx.x >> 5;
        const int lane = threadIdx.x & 31;
        const int site0 = sg * 32 + warp * 4;

        // stage 9 planes: w0,w1,w2, w00,w01,w02, w11,w12,w22
        for (int vv = threadIdx.x; vv < 1024; vv += 256) {
            const float* wp = W + (size_t)(e * 1024 + vv) * 3;
            float w0 = wp[0], w1 = wp[1], w2 = wp[2];
            buf[0 * 1024 + vv] = w0;
            buf[1 * 1024 + vv] = w1;
            buf[2 * 1024 + vv] = w2;
            buf[3 * 1024 + vv] = w0 * w0;
            buf[4 * 1024 + vv] = w0 * w1;
            buf[5 * 1024 + vv] = w0 * w2;
            buf[6 * 1024 + vv] = w1 * w1;
            buf[7 * 1024 + vv] = w1 * w2;
            buf[8 * 1024 + vv] = w2 * w2;
        }
        __syncthreads();

        const float LOG2E = 1.4426950408889634f;
        ull mu0[4], mu1[4], mu2[4];
#pragma unroll
        for (int s = 0; s < 4; s++) {
            float a = mu[(site0 + s) * 3 + 0] * LOG2E;
            float b = mu[(site0 + s) * 3 + 1] * LOG2E;
            float c = mu[(site0 + s) * 3 + 2] * LOG2E;
            mu0[s] = pk2(a, a);
            mu1[s] = pk2(b, b);
            mu2[s] = pk2(c, c);
        }

        ull acc[4][10];
#pragma unroll
        for (int s = 0; s < 4; s++)
#pragma unroll
            for (int k = 0; k < 10; k++) acc[s][k] = 0ull;

        for (int it = 0; it < 8; it++) {
            const int v = it * 128 + lane * 4;
            ulonglong2 p[9];
#pragma unroll
            for (int k = 0; k < 9; k++)
                p[k] = *(const ulonglong2*)&buf[k * 1024 + v];
#pragma unroll
            for (int h = 0; h < 2; h++) {
                ull w0p = h ? p[0].y : p[0].x;
                ull w1p = h ? p[1].y : p[1].x;
                ull w2p = h ? p[2].y : p[2].x;
#pragma unroll
                for (int s = 0; s < 4; s++) {
                    ull l = fma2(mu0[s], w0p, fma2(mu1[s], w1p, mul2(mu2[s], w2p)));
                    float l0, l1;
                    upk2(l, l0, l1);
                    ull ep = pk2(ex2f(l0), ex2f(l1));
                    acc[s][0] = add2(acc[s][0], ep);
                    acc[s][1] = fma2(ep, w0p, acc[s][1]);
                    acc[s][2] = fma2(ep, w1p, acc[s][2]);
                    acc[s][3] = fma2(ep, w2p, acc[s][3]);
                    acc[s][4] = fma2(ep, h ? p[3].y : p[3].x, acc[s][4]);
                    acc[s][5] = fma2(ep, h ? p[4].y : p[4].x, acc[s][5]);
                    acc[s][6] = fma2(ep, h ? p[5].y : p[5].x, acc[s][6]);
                    acc[s][7] = fma2(ep, h ? p[6].y : p[6].x, acc[s][7]);
                    acc[s][8] = fma2(ep, h ? p[7].y : p[7].x, acc[s][8]);
                    acc[s][9] = fma2(ep, h ? p[8].y : p[8].x, acc[s][9]);
                }
            }
        }

        float st[4][10];
#pragma unroll
        for (int s = 0; s < 4; s++)
#pragma unroll
            for (int k = 0; k < 10; k++) {
                float lo, hi;
                upk2(acc[s][k], lo, hi);
                st[s][k] = lo + hi;
            }
#pragma unroll
        for (int s = 0; s < 4; s++)
#pragma unroll
            for (int k = 0; k < 10; k++)
#pragma unroll
                for (int off = 16; off; off >>= 1)
                    st[s][k] += __shfl_xor_sync(~0u, st[s][k], off);

        if (lane < 4) {
            float* dst = g_sm + ((size_t)e * NS + site0 + lane) * 12;
#pragma unroll
            for (int k = 0; k < 10; k++) dst[k] = st[lane][k];
        }
    }
}

// ==== FINAL: 16 threads/site cooperative reduction, assemble M, invert ====
// 128 blocks x 256 threads.
__global__ void __launch_bounds__(256) final_kernel(float* __restrict__ out) {
    const int i = blockIdx.x * 16 + (threadIdx.x >> 4);
    const int sub = threadIdx.x & 15;

    float st[10];
#pragma unroll
    for (int k = 0; k < 10; k++) st[k] = 0.f;
    float C[9];
#pragma unroll
    for (int k = 0; k < 9; k++) C[k] = 0.f;

    if (sub < 8) {
        // one softmax partial
        const float4* src = (const float4*)(g_sm + ((size_t)sub * NS + i) * 12);
        float4 v0 = src[0], v1 = src[1], v2 = src[2];
        st[0] = v0.x; st[1] = v0.y; st[2] = v0.z; st[3] = v0.w;
        st[4] = v1.x; st[5] = v1.y; st[6] = v1.z; st[7] = v1.w;
        st[8] = v2.x; st[9] = v2.y;
    } else {
        // one C chunk
        const float4* src = (const float4*)(g_Cpart + ((size_t)(sub - 8) * NS + i) * 12);
        float4 v0 = src[0], v1 = src[1], v2 = src[2];
        C[0] = v0.x; C[1] = v0.y; C[2] = v0.z; C[3] = v0.w;
        C[4] = v1.x; C[5] = v1.y; C[6] = v1.z; C[7] = v1.w;
        C[8] = v2.x;
    }

    // colsum: 2 of 32 float4s per sub-lane
    float cs = 0.f;
    {
        const float4* src = (const float4*)(g_colp + (size_t)i * 128) + sub * 2;
        float4 v0 = src[0], v1 = src[1];
        cs = v0.x + v0.y + v0.z + v0.w + v1.x + v1.y + v1.z + v1.w;
    }

    // combine across the 16 sub-lanes (aligned group)
#pragma unroll
    for (int off = 1; off <= 8; off <<= 1) {
#pragma unroll
        for (int k = 0; k < 10; k++) st[k] += __shfl_xor_sync(~0u, st[k], off);
#pragma unroll
        for (int k = 0; k < 9; k++) C[k] += __shfl_xor_sync(~0u, C[k], off);
        cs += __shfl_xor_sync(~0u, cs, off);
    }

    if (sub == 0) {
        float Zi = 1.0f / st[0];
        float m0 = st[1] * Zi, m1 = st[2] * Zi, m2 = st[3] * Zi;
        float Lo[9];
        Lo[0] = st[4] * Zi - m0 * m0 + 1e-6f;
        Lo[1] = st[5] * Zi - m0 * m1;
        Lo[2] = st[6] * Zi - m0 * m2;
        Lo[3] = Lo[1];
        Lo[4] = st[7] * Zi - m1 * m1 + 1e-6f;
        Lo[5] = st[8] * Zi - m1 * m2;
        Lo[6] = Lo[2];
        Lo[7] = Lo[5];
        Lo[8] = st[9] * Zi - m2 * m2 + 1e-6f;

        float R[9], Lq[9], Ab[9];
        {
            const float4* r4 = (const float4*)(g_R + (size_t)i * 12);
            float4 v0 = r4[0], v1 = r4[1], v2 = r4[2];
            R[0] = v0.x; R[1] = v0.y; R[2] = v0.z; R[3] = v0.w;
            R[4] = v1.x; R[5] = v1.y; R[6] = v1.z; R[7] = v1.w;
            R[8] = v2.x;
            const float4* q4 = (const float4*)(g_Lq + (size_t)i * 12);
            v0 = q4[0]; v1 = q4[1]; v2 = q4[2];
            Lq[0] = v0.x; Lq[1] = v0.y; Lq[2] = v0.z; Lq[3] = v0.w;
            Lq[4] = v1.x; Lq[5] = v1.y; Lq[6] = v1.z; Lq[7] = v1.w;
            Lq[8] = v2.x;
            const float4* p4 = (const float4*)(g_Lp + (size_t)i * 12);
            v0 = p4[0]; v1 = p4[1]; v2 = p4[2];
            Ab[0] = v0.x + Lo[0]; Ab[1] = v0.y + Lo[1]; Ab[2] = v0.z + Lo[2];
            Ab[3] = v0.w + Lo[3]; Ab[4] = v1.x + Lo[4]; Ab[5] = v1.y + Lo[5];
            Ab[6] = v1.z + Lo[6]; Ab[7] = v1.w + Lo[7]; Ab[8] = v2.x + Lo[8];
        }

        float T[9], Min[9];
        mm3(R, C, T);
        mmT3(T, R, Min);

        float M[9];
#pragma unroll
        for (int k = 0; k < 9; k++) M[k] = Ab[k] + Min[k] + cs * Lq[k];

        float Ms[9];
#pragma unroll
        for (int r = 0; r < 3; r++)
#pragma unroll
            for (int cc = 0; cc < 3; cc++)
                Ms[r * 3 + cc] = 0.5f * (M[r * 3 + cc] + M[cc * 3 + r]);

#pragma unroll
        for (int k = 0; k < 9; k++)
            if (!isfinite(Ms[k])) Ms[k] = (k == 0 || k == 4 || k == 8) ? 1.0f : 0.0f;
        Ms[0] += 1e-4f; Ms[4] += 1e-4f; Ms[8] += 1e-4f;

        float Mi[9];
        inv3(Ms, Mi);

#pragma unroll
        for (int k = 0; k < 9; k++) {
            out[i * 9 + k] = Ms[k];
            out[NS * 9 + i * 9 + k] = Mi[k];
        }
    }
}

extern "C" void kernel_launch(void* const* d_in, const int* in_sizes, int n_in,
                              void* d_out, int out_size) {
    const float* Sp = (const float*)d_in[0];
    const float* Sq = (const float*)d_in[1];
    const float* phi = (const float*)d_in[2];
    const float* beta = (const float*)d_in[3];
    const float* mu = (const float*)d_in[4];
    const float* W = (const float*)d_in[5];
    float* out = (float*)d_out;

    mega_kernel<<<1544, 256>>>(Sp, Sq, phi, mu, W, beta);
    final_kernel<<<128, 256>>>(out);
}

// round 13
// speedup vs baseline: 1.4321x; 1.4321x over previous
#include <cuda_runtime.h>
#include <math.h>

#define NS 2048

// ---- scratch (device globals) ----
__device__ float g_sm[NS * 12];          // softmax stats [site][10 of 12]
__device__ float g_colT[NS * 32];        // colsum partials transposed [j][b]
__device__ float g_Cpart[8 * NS * 12];   // beta@S partials [chunk][row][9 of 12]

// ---- packed f32x2 helpers ----
typedef unsigned long long ull;
__device__ __forceinline__ ull pk2(float a, float b) {
    ull r; asm("mov.b64 %0, {%1,%2};" : "=l"(r) : "f"(a), "f"(b)); return r;
}
__device__ __forceinline__ void upk2(ull p, float& a, float& b) {
    asm("mov.b64 {%0,%1}, %2;" : "=f"(a), "=f"(b) : "l"(p));
}
__device__ __forceinline__ ull fma2(ull a, ull b, ull c) {
    ull r; asm("fma.rn.f32x2 %0, %1, %2, %3;" : "=l"(r) : "l"(a), "l"(b), "l"(c)); return r;
}
__device__ __forceinline__ ull mul2(ull a, ull b) {
    ull r; asm("mul.rn.f32x2 %0, %1, %2;" : "=l"(r) : "l"(a), "l"(b)); return r;
}
__device__ __forceinline__ ull add2(ull a, ull b) {
    ull r; asm("add.rn.f32x2 %0, %1, %2;" : "=l"(r) : "l"(a), "l"(b)); return r;
}
__device__ __forceinline__ float ex2f(float x) {
    float r; asm("ex2.approx.f32 %0, %1;" : "=f"(r) : "f"(x)); return r;
}

// ---- 3x3 helpers ----
__device__ __forceinline__ void inv3(const float* a, float* o) {
    float c00 = a[4] * a[8] - a[5] * a[7];
    float c01 = a[5] * a[6] - a[3] * a[8];
    float c02 = a[3] * a[7] - a[4] * a[6];
    float det = a[0] * c00 + a[1] * c01 + a[2] * c02;
    float id = 1.0f / det;
    o[0] = c00 * id;
    o[1] = (a[2] * a[7] - a[1] * a[8]) * id;
    o[2] = (a[1] * a[5] - a[2] * a[4]) * id;
    o[3] = c01 * id;
    o[4] = (a[0] * a[8] - a[2] * a[6]) * id;
    o[5] = (a[2] * a[3] - a[0] * a[5]) * id;
    o[6] = c02 * id;
    o[7] = (a[1] * a[6] - a[0] * a[7]) * id;
    o[8] = (a[0] * a[4] - a[1] * a[3]) * id;
}
__device__ __forceinline__ void mm3(const float* A, const float* B, float* O) {
#pragma unroll
    for (int r = 0; r < 3; r++)
#pragma unroll
        for (int c = 0; c < 3; c++)
            O[r * 3 + c] = A[r * 3 + 0] * B[0 + c] + A[r * 3 + 1] * B[3 + c] + A[r * 3 + 2] * B[6 + c];
}
__device__ __forceinline__ void mTm3(const float* A, const float* B, float* O) {
#pragma unroll
    for (int r = 0; r < 3; r++)
#pragma unroll
        for (int c = 0; c < 3; c++)
            O[r * 3 + c] = A[0 + r] * B[0 + c] + A[3 + r] * B[3 + c] + A[6 + r] * B[6 + c];
}
__device__ __forceinline__ void mmT3(const float* A, const float* B, float* O) {
#pragma unroll
    for (int r = 0; r < 3; r++)
#pragma unroll
        for (int c = 0; c < 3; c++)
            O[r * 3 + c] = A[r * 3 + 0] * B[c * 3 + 0] + A[r * 3 + 1] * B[c * 3 + 1] + A[r * 3 + 2] * B[c * 3 + 2];
}
__device__ __forceinline__ void rodrigues(float x, float y, float z, float* R) {
    float t2 = x * x + y * y + z * z;
    float A, B;
    if (t2 < 1e-12f) {
        A = 1.0f - t2 * (1.0f / 6.0f);
        B = 0.5f - t2 * (1.0f / 24.0f);
    } else {
        float t = sqrtf(t2);
        A = sinf(t) / t;
        B = (1.0f - cosf(t)) / t2;
    }
    R[0] = 1.0f - B * (y * y + z * z);
    R[1] = -A * z + B * x * y;
    R[2] = A * y + B * x * z;
    R[3] = A * z + B * x * y;
    R[4] = 1.0f - B * (x * x + z * z);
    R[5] = -A * x + B * y * z;
    R[6] = -A * y + B * x * z;
    R[7] = A * x + B * y * z;
    R[8] = 1.0f - B * (x * x + y * y);
}

// S = R^T inv(Sq+eps) R for one site
__device__ __forceinline__ void site_S(const float* __restrict__ Sq,
                                       const float* __restrict__ phi,
                                       int site, float* Smat) {
    float a[9], Lq[9];
#pragma unroll
    for (int k = 0; k < 9; k++) a[k] = Sq[site * 9 + k];
    a[0] += 1e-6f; a[4] += 1e-6f; a[8] += 1e-6f;
    inv3(a, Lq);
    float R[9];
    rodrigues(phi[site * 3 + 0], phi[site * 3 + 1], phi[site * 3 + 2], R);
    float T[9];
    mm3(Lq, R, T);
    mTm3(R, T, Smat);
}

// ==== MEGA kernel ====
// blocks 0..255   : softmax stats (1 site/warp, full V, R2-proven structure)
// blocks 256..287 : beta colsum partials (transposed)
// blocks 288..1311: beta@S GEMM partials (local S, split-K 8)
__global__ void __launch_bounds__(256) mega_kernel(
    const float* __restrict__ Sq, const float* __restrict__ phi,
    const float* __restrict__ mu, const float* __restrict__ W,
    const float* __restrict__ beta) {
    __shared__ float buf[6144];

    if (blockIdx.x < 256) {
        // ---------------- softmax (warp = site, 4 chunk loop) ----------------
        const int warp = threadIdx.x >> 5;
        const int lane = threadIdx.x & 31;
        const int site = blockIdx.x * 8 + warp;

        const float LOG2E = 1.4426950408889634f;
        const float mu0 = mu[site * 3 + 0] * LOG2E;
        const float mu1 = mu[site * 3 + 1] * LOG2E;
        const float mu2 = mu[site * 3 + 2] * LOG2E;
        const ull mu0p = pk2(mu0, mu0), mu1p = pk2(mu1, mu1), mu2p = pk2(mu2, mu2);

        float* sW0 = buf;
        float* sW1 = buf + 2048;
        float* sW2 = buf + 4096;

        ull Z2 = 0ull, sw0p = 0ull, sw1p = 0ull, sw2p = 0ull;
        ull s00p = 0ull, s01p = 0ull, s02p = 0ull, s11p = 0ull, s12p = 0ull, s22p = 0ull;

        for (int ch = 0; ch < 4; ch++) {
            __syncthreads();
            for (int vv = threadIdx.x; vv < 2048; vv += 256) {
                const float* wp = W + (size_t)(ch * 2048 + vv) * 3;
                sW0[vv] = wp[0];
                sW1[vv] = wp[1];
                sW2[vv] = wp[2];
            }
            __syncthreads();
#pragma unroll 2
            for (int it = 0; it < 16; it++) {
                int v = it * 128 + lane * 4;
                float4 w0 = *(const float4*)&sW0[v];
                float4 w1 = *(const float4*)&sW1[v];
                float4 w2 = *(const float4*)&sW2[v];
#pragma unroll
                for (int h = 0; h < 2; h++) {
                    ull w0p = h ? pk2(w0.z, w0.w) : pk2(w0.x, w0.y);
                    ull w1p = h ? pk2(w1.z, w1.w) : pk2(w1.x, w1.y);
                    ull w2p = h ? pk2(w2.z, w2.w) : pk2(w2.x, w2.y);
                    ull l = fma2(mu0p, w0p, fma2(mu1p, w1p, mul2(mu2p, w2p)));
                    float l0, l1;
                    upk2(l, l0, l1);
                    ull ep = pk2(ex2f(l0), ex2f(l1));
                    Z2 = add2(Z2, ep);
                    ull t0 = mul2(ep, w0p);
                    ull t1 = mul2(ep, w1p);
                    ull t2 = mul2(ep, w2p);
                    sw0p = add2(sw0p, t0);
                    sw1p = add2(sw1p, t1);
                    sw2p = add2(sw2p, t2);
                    s00p = fma2(t0, w0p, s00p);
                    s01p = fma2(t0, w1p, s01p);
                    s02p = fma2(t0, w2p, s02p);
                    s11p = fma2(t1, w1p, s11p);
                    s12p = fma2(t1, w2p, s12p);
                    s22p = fma2(t2, w2p, s22p);
                }
            }
        }

        float st[10];
        float x, y;
        upk2(Z2, x, y);   st[0] = x + y;
        upk2(sw0p, x, y); st[1] = x + y;
        upk2(sw1p, x, y); st[2] = x + y;
        upk2(sw2p, x, y); st[3] = x + y;
        upk2(s00p, x, y); st[4] = x + y;
        upk2(s01p, x, y); st[5] = x + y;
        upk2(s02p, x, y); st[6] = x + y;
        upk2(s11p, x, y); st[7] = x + y;
        upk2(s12p, x, y); st[8] = x + y;
        upk2(s22p, x, y); st[9] = x + y;

#pragma unroll
        for (int k = 0; k < 10; k++)
#pragma unroll
            for (int off = 16; off; off >>= 1)
                st[k] += __shfl_xor_sync(~0u, st[k], off);

        if (lane == 0) {
            float* dst = g_sm + (size_t)site * 12;
#pragma unroll
            for (int k = 0; k < 10; k++) dst[k] = st[k];
        }
        return;
    }

    if (blockIdx.x < 288) {
        // ---------------- colsum: 32 blocks, 64 rows each, transposed out ----
        const int b = blockIdx.x - 256;
        const int i0 = b * 64;
        const int t = threadIdx.x;
        float4 a0 = make_float4(0.f, 0.f, 0.f, 0.f);
        float4 a1 = make_float4(0.f, 0.f, 0.f, 0.f);
#pragma unroll 4
        for (int i = 0; i < 64; i++) {
            const float4* row = (const float4*)(beta + (size_t)(i0 + i) * NS);
            float4 v0 = row[t];
            float4 v1 = row[t + 256];
            a0.x += v0.x; a0.y += v0.y; a0.z += v0.z; a0.w += v0.w;
            a1.x += v1.x; a1.y += v1.y; a1.z += v1.z; a1.w += v1.w;
        }
        int j0 = t * 4;
        g_colT[(j0 + 0) * 32 + b] = a0.x;
        g_colT[(j0 + 1) * 32 + b] = a0.y;
        g_colT[(j0 + 2) * 32 + b] = a0.z;
        g_colT[(j0 + 3) * 32 + b] = a0.w;
        g_colT[(j0 + 1024) * 32 + b] = a1.x;
        g_colT[(j0 + 1025) * 32 + b] = a1.y;
        g_colT[(j0 + 1026) * 32 + b] = a1.z;
        g_colT[(j0 + 1027) * 32 + b] = a1.w;
        return;
    }

    // ---------------- GEMM partials (split-K 8, local S) ----------------
    {
        const int t = blockIdx.x - 288;
        const int chunk = t & 7;
        const int rg = t >> 3;
        const int j0 = chunk * 256;
        const int warp = threadIdx.x >> 5;
        const int lane = threadIdx.x & 31;
        const int row0 = rg * 16 + warp * 2;

        float* sS = buf;  // [9][264]
        {
            float Smat[9];
            site_S(Sq, phi, j0 + threadIdx.x, Smat);
#pragma unroll
            for (int k = 0; k < 9; k++) sS[k * 264 + threadIdx.x] = Smat[k];
        }
        __syncthreads();

        const int jj = lane * 8;
        const float* b0p = beta + (size_t)row0 * NS + j0 + jj;
        const float* b1p = b0p + NS;
        ulonglong2 b0 = *(const ulonglong2*)b0p;
        ulonglong2 b0h = *(const ulonglong2*)(b0p + 4);
        ulonglong2 b1 = *(const ulonglong2*)b1p;
        ulonglong2 b1h = *(const ulonglong2*)(b1p + 4);

        float c[2][9];
#pragma unroll
        for (int k = 0; k < 9; k++) {
            ulonglong2 sa = *(const ulonglong2*)&sS[k * 264 + jj];
            ulonglong2 sb = *(const ulonglong2*)&sS[k * 264 + jj + 4];
            ull a0 = fma2(b0.x, sa.x, mul2(b0.y, sa.y));
            a0 = fma2(b0h.x, sb.x, a0);
            a0 = fma2(b0h.y, sb.y, a0);
            ull a1 = fma2(b1.x, sa.x, mul2(b1.y, sa.y));
            a1 = fma2(b1h.x, sb.x, a1);
            a1 = fma2(b1h.y, sb.y, a1);
            float lo, hi;
            upk2(a0, lo, hi);
            c[0][k] = lo + hi;
            upk2(a1, lo, hi);
            c[1][k] = lo + hi;
        }

#pragma unroll
        for (int r = 0; r < 2; r++)
#pragma unroll
            for (int k = 0; k < 9; k++)
#pragma unroll
                for (int off = 16; off; off >>= 1)
                    c[r][k] += __shfl_xor_sync(~0u, c[r][k], off);

        if (lane < 2) {
            const int row = row0 + lane;
            float* dst = g_Cpart + ((size_t)chunk * NS + row) * 12;
#pragma unroll
            for (int k = 0; k < 9; k++) dst[k] = c[lane][k];
        }
    }
}

// ==== FINAL: 16 threads/site; reduce partials, geometry inline, invert ====
// 128 blocks x 256 threads.
__global__ void __launch_bounds__(256) final_kernel(
    const float* __restrict__ Sp, const float* __restrict__ Sq,
    const float* __restrict__ phi, float* __restrict__ out) {
    const int i = blockIdx.x * 16 + (threadIdx.x >> 4);
    const int sub = threadIdx.x & 15;

    float st[10];
#pragma unroll
    for (int k = 0; k < 10; k++) st[k] = 0.f;
    float C[9];
#pragma unroll
    for (int k = 0; k < 9; k++) C[k] = 0.f;
    float cs = 0.f;

    if (sub < 8) {
        // one C chunk
        const float4* src = (const float4*)(g_Cpart + ((size_t)sub * NS + i) * 12);
        float4 v0 = src[0], v1 = src[1], v2 = src[2];
        C[0] = v0.x; C[1] = v0.y; C[2] = v0.z; C[3] = v0.w;
        C[4] = v1.x; C[5] = v1.y; C[6] = v1.z; C[7] = v1.w;
        C[8] = v2.x;
        if (sub == 0) {
            const float4* s4 = (const float4*)(g_sm + (size_t)i * 12);
            float4 u0 = s4[0], u1 = s4[1], u2 = s4[2];
            st[0] = u0.x; st[1] = u0.y; st[2] = u0.z; st[3] = u0.w;
            st[4] = u1.x; st[5] = u1.y; st[6] = u1.z; st[7] = u1.w;
            st[8] = u2.x; st[9] = u2.y;
        }
    } else {
        // colsum: one float4 of the 32 transposed partials
        float4 v = *(const float4*)(g_colT + (size_t)i * 32 + (sub - 8) * 4);
        cs = v.x + v.y + v.z + v.w;
    }

    // combine across the 16 sub-lanes (aligned group)
#pragma unroll
    for (int off = 1; off <= 8; off <<= 1) {
#pragma unroll
        for (int k = 0; k < 10; k++) st[k] += __shfl_xor_sync(~0u, st[k], off);
#pragma unroll
        for (int k = 0; k < 9; k++) C[k] += __shfl_xor_sync(~0u, C[k], off);
        cs += __shfl_xor_sync(~0u, cs, off);
    }

    if (sub == 0) {
        float Zi = 1.0f / st[0];
        float m0 = st[1] * Zi, m1 = st[2] * Zi, m2 = st[3] * Zi;
        float Lo[9];
        Lo[0] = st[4] * Zi - m0 * m0 + 1e-6f;
        Lo[1] = st[5] * Zi - m0 * m1;
        Lo[2] = st[6] * Zi - m0 * m2;
        Lo[3] = Lo[1];
        Lo[4] = st[7] * Zi - m1 * m1 + 1e-6f;
        Lo[5] = st[8] * Zi - m1 * m2;
        Lo[6] = Lo[2];
        Lo[7] = Lo[5];
        Lo[8] = st[9] * Zi - m2 * m2 + 1e-6f;

        // geometry inline
        float a[9], Lp[9], Lq[9];
#pragma unroll
        for (int k = 0; k < 9; k++) a[k] = Sp[i * 9 + k];
        a[0] += 1e-6f; a[4] += 1e-6f; a[8] += 1e-6f;
        inv3(a, Lp);
#pragma unroll
        for (int k = 0; k < 9; k++) a[k] = Sq[i * 9 + k];
        a[0] += 1e-6f; a[4] += 1e-6f; a[8] += 1e-6f;
        inv3(a, Lq);
        float R[9];
        rodrigues(phi[i * 3 + 0], phi[i * 3 + 1], phi[i * 3 + 2], R);

        float T[9], Min[9];
        mm3(R, C, T);
        mmT3(T, R, Min);

        float M[9];
#pragma unroll
        for (int k = 0; k < 9; k++) M[k] = Lp[k] + Lo[k] + Min[k] + cs * Lq[k];

        float Ms[9];
#pragma unroll
        for (int r = 0; r < 3; r++)
#pragma unroll
            for (int cc = 0; cc < 3; cc++)
                Ms[r * 3 + cc] = 0.5f * (M[r * 3 + cc] + M[cc * 3 + r]);

#pragma unroll
        for (int k = 0; k < 9; k++)
            if (!isfinite(Ms[k])) Ms[k] = (k == 0 || k == 4 || k == 8) ? 1.0f : 0.0f;
        Ms[0] += 1e-4f; Ms[4] += 1e-4f; Ms[8] += 1e-4f;

        float Mi[9];
        inv3(Ms, Mi);

#pragma unroll
        for (int k = 0; k < 9; k++) {
            out[i * 9 + k] = Ms[k];
            out[NS * 9 + i * 9 + k] = Mi[k];
        }
    }
}

extern "C" void kernel_launch(void* const* d_in, const int* in_sizes, int n_in,
                              void* d_out, int out_size) {
    const float* Sp = (const float*)d_in[0];
    const float* Sq = (const float*)d_in[1];
    const float* phi = (const float*)d_in[2];
    const float* beta = (const float*)d_in[3];
    const float* mu = (const float*)d_in[4];
    const float* W = (const float*)d_in[5];
    float* out = (float*)d_out;

    mega_kernel<<<1312, 256>>>(Sq, phi, mu, W, beta);
    final_kernel<<<128, 256>>>(Sp, Sq, phi, out);
}